// round 7
// baseline (speedup 1.0000x reference)
#include <cuda_runtime.h>

// Row size in elements: C*W*H = 512*7*7 (fixed per metadata).
#define ROW_ELEMS 25088
#define ROW_VEC4  (ROW_ELEMS / 4)   // 6272 float4 per row
#define QTR_VEC4  (ROW_VEC4 / 4)    // 1568 float4 per quarter-row (25 KB)

// One block per output QUARTER-row. Granularity sweep: full-row (R3,
// 121.6us) -> half-row (R5, 119.1us) -> quarter-row (this). Copy loop and
// cache policy identical to R3/R5 (plain float4; .cs regressed in R2,
// persistent grid regressed in R4).
__global__ void __launch_bounds__(256) gather_qtr_kernel(
    const float4* __restrict__ in, float4* __restrict__ out,
    const int* __restrict__ obj_num, int n_images) {

    int bq = blockIdx.x;
    int r  = bq >> 2;               // output row index = 3*p + j
    int qv = (bq & 3) * QTR_VEC4;   // quarter offset in vec4 units

    int p = r / 3;             // global pair index
    int j = r - 3 * p;         // 0 = o1 feat, 1 = o2 feat, 2 = union feat

    // Locate the image containing pair p (n_images <= 16; obj_num L1-resident
    // after first touch).
    int pair_base = 0;         // pairs before this image
    int row_begin = 0;         // input rows before this image
    int n = 0;
    for (int i = 0; i < n_images; ++i) {
        n = obj_num[i];
        int np = n * (n - 1) / 2;
        if (p < pair_base + np) break;
        pair_base += np;
        row_begin += n * (n + 1) / 2;
    }
    int u = p - pair_base;     // pair index within image

    // Invert row-major triangular enumeration to (o1, o2).
    int o1 = 0, s = 0;
    while (s + (n - 1 - o1) <= u) {
        s += (n - 1 - o1);
        ++o1;
    }
    int o2 = o1 + 1 + (u - s);

    int src_row = (j == 0) ? (row_begin + o1)
                : (j == 1) ? (row_begin + o2)
                           : (row_begin + n + u);

    const float4* __restrict__ src = in + (long long)src_row * ROW_VEC4 + qv;
    float4* __restrict__ dst = out + (long long)r * ROW_VEC4 + qv;

    #pragma unroll 8
    for (int i = threadIdx.x; i < QTR_VEC4; i += 256) {
        dst[i] = src[i];
    }
}

extern "C" void kernel_launch(void* const* d_in, const int* in_sizes, int n_in,
                              void* d_out, int out_size) {
    const float* feats = (const float*)d_in[0];
    // d_in[1] is batch_size scalar; d_in[2] is obj_num array.
    const int* obj_num = (const int*)d_in[2];
    int n_images = in_sizes[2];

    int out_rows = out_size / ROW_ELEMS;      // = 3 * P

    gather_qtr_kernel<<<out_rows * 4, 256>>>((const float4*)feats,
                                             (float4*)d_out,
                                             obj_num, n_images);
}

// round 8
// speedup vs baseline: 1.0898x; 1.0898x over previous
#include <cuda_runtime.h>

// Row size in elements: C*W*H = 512*7*7 (fixed per metadata).
#define ROW_ELEMS 25088
#define ROW_VEC4  (ROW_ELEMS / 4)   // 6272 float4 per row
#define HALF_VEC4 (ROW_VEC4 / 2)    // 3136 float4 per half-row (50 KB)
// 3136 = 12*256 + 64 : three 4-deep batches + 64-thread tail.

// One block per output HALF-row (granularity sweep winner: full 121.6us,
// half 119.1us, quarter 130.7us). Plain float4, no cache hints (.cs
// regressed R2; persistent grid regressed R4). New vs R5: inner loop issues
// 4 LDG.128 before their 4 STG.128 to raise per-warp MLP (R7 showed BW
// tracks loads-in-flight).
__global__ void __launch_bounds__(256) gather_half_kernel(
    const float4* __restrict__ in, float4* __restrict__ out,
    const int* __restrict__ obj_num, int n_images) {

    int br = blockIdx.x;
    int r  = br >> 1;               // output row index = 3*p + j
    int hv = (br & 1) * HALF_VEC4;  // half offset in vec4 units

    int p = r / 3;             // global pair index
    int j = r - 3 * p;         // 0 = o1 feat, 1 = o2 feat, 2 = union feat

    // Locate the image containing pair p (n_images <= 16; obj_num L1-resident
    // after first touch).
    int pair_base = 0;         // pairs before this image
    int row_begin = 0;         // input rows before this image
    int n = 0;
    for (int i = 0; i < n_images; ++i) {
        n = obj_num[i];
        int np = n * (n - 1) / 2;
        if (p < pair_base + np) break;
        pair_base += np;
        row_begin += n * (n + 1) / 2;
    }
    int u = p - pair_base;     // pair index within image

    // Invert row-major triangular enumeration to (o1, o2).
    int o1 = 0, s = 0;
    while (s + (n - 1 - o1) <= u) {
        s += (n - 1 - o1);
        ++o1;
    }
    int o2 = o1 + 1 + (u - s);

    int src_row = (j == 0) ? (row_begin + o1)
                : (j == 1) ? (row_begin + o2)
                           : (row_begin + n + u);

    const float4* __restrict__ src = in + (long long)src_row * ROW_VEC4 + hv;
    float4* __restrict__ dst = out + (long long)r * ROW_VEC4 + hv;

    int tid = threadIdx.x;

    // 3 batches x (4 loads then 4 stores) covering 3072 vec4.
    #pragma unroll
    for (int base = 0; base < 3072; base += 1024) {
        float4 v0 = src[base + tid];
        float4 v1 = src[base + tid + 256];
        float4 v2 = src[base + tid + 512];
        float4 v3 = src[base + tid + 768];
        dst[base + tid]       = v0;
        dst[base + tid + 256] = v1;
        dst[base + tid + 512] = v2;
        dst[base + tid + 768] = v3;
    }
    // Tail: remaining 64 vec4.
    int t = 3072 + tid;
    if (t < HALF_VEC4) {
        dst[t] = src[t];
    }
}

extern "C" void kernel_launch(void* const* d_in, const int* in_sizes, int n_in,
                              void* d_out, int out_size) {
    const float* feats = (const float*)d_in[0];
    // d_in[1] is batch_size scalar; d_in[2] is obj_num array.
    const int* obj_num = (const int*)d_in[2];
    int n_images = in_sizes[2];

    int out_rows = out_size / ROW_ELEMS;      // = 3 * P

    gather_half_kernel<<<out_rows * 2, 256>>>((const float4*)feats,
                                              (float4*)d_out,
                                              obj_num, n_images);
}